// round 1
// baseline (speedup 1.0000x reference)
#include <cuda_runtime.h>
#include <math.h>

#define NN 49920
#define EE 200000
#define BB 128
#define C1 256          // per-head out, layer1
#define C2 64           // per-head out, layer2
#define HH 4
#define D1 1024         // HH*C1
#define D2 256          // HH*C2

// ---------------- scratch (device globals; no allocation allowed) ----------------
__device__ float g_xl1[(size_t)NN * D1];
__device__ float g_xr1[(size_t)NN * D1];
__device__ float g_ef1[(size_t)EE * D1];
__device__ float g_h1 [(size_t)NN * D1];
__device__ float g_xl2[(size_t)NN * D2];
__device__ float g_xr2[(size_t)NN * D2];
__device__ float g_ef2[(size_t)EE * D2];
__device__ float g_h2 [(size_t)NN * D2];

__device__ int g_src[EE];
__device__ int g_dst[EE];
__device__ int g_cnt[NN];
__device__ int g_cur[NN];
__device__ int g_offs[NN + 1];
__device__ int g_perm[EE];

// ---------------- CSR build ----------------
__global__ void k_zero()
{
    int i = blockIdx.x * blockDim.x + threadIdx.x;
    if (i < NN) { g_cnt[i] = 0; g_cur[i] = 0; }
}

// edge_index may arrive as int64 or int32 (JAX x64 off demotes). Detect:
// for int64 little-endian values < 2^32, odd 32-bit words are all zero.
__global__ void k_convert(const void* __restrict__ ei)
{
    int e = blockIdx.x * blockDim.x + threadIdx.x;
    if (e >= EE) return;
    const int* w = (const int*)ei;
    bool is64 = true;
#pragma unroll
    for (int i = 1; i < 16; i += 2) is64 = is64 && (w[i] == 0);
    if (is64) {
        const long long* l = (const long long*)ei;
        g_src[e] = (int)l[e];
        g_dst[e] = (int)l[(size_t)EE + e];
    } else {
        g_src[e] = w[e];
        g_dst[e] = w[EE + e];
    }
}

__global__ void k_count()
{
    int e = blockIdx.x * blockDim.x + threadIdx.x;
    if (e < EE) atomicAdd(&g_cnt[g_dst[e]], 1);
}

__global__ void k_scan()  // single block, 1024 threads
{
    __shared__ int part[1024];
    const int t = threadIdx.x;
    const int CH = (NN + 1023) / 1024;
    int base = t * CH;
    int s = 0;
    for (int i = 0; i < CH; i++) { int idx = base + i; if (idx < NN) s += g_cnt[idx]; }
    part[t] = s;
    __syncthreads();
    for (int off = 1; off < 1024; off <<= 1) {
        int v = part[t];
        int add = (t >= off) ? part[t - off] : 0;
        __syncthreads();
        part[t] = v + add;
        __syncthreads();
    }
    int run = (t == 0) ? 0 : part[t - 1];
    for (int i = 0; i < CH; i++) {
        int idx = base + i;
        if (idx < NN) { g_offs[idx] = run; run += g_cnt[idx]; }
    }
    if (t == 1023) g_offs[NN] = part[1023];
}

__global__ void k_scatter()
{
    int e = blockIdx.x * blockDim.x + threadIdx.x;
    if (e >= EE) return;
    int d = g_dst[e];
    int p = g_offs[d] + atomicAdd(&g_cur[d], 1);
    g_perm[p] = e;
}

// ---------------- fp32 GEMM: C[M,Ncol] = A[M,K] @ B[K,Ncol] (+ bias) ----------------
// BM=BN=128, BK=16, 256 threads, 8x8 per-thread tile. M may be non-multiple of 128;
// K multiple of 16 and Ncol multiple of 128 always hold for this problem.
__global__ __launch_bounds__(256) void k_gemm(const float* __restrict__ A,
                                              const float* __restrict__ B,
                                              const float* __restrict__ bias,
                                              float* __restrict__ C,
                                              int M, int K, int Ncol)
{
    __shared__ float As[16][128];
    __shared__ float Bs[16][128];
    const int tid = threadIdx.x;
    const int tx = tid & 15, ty = tid >> 4;
    const int m0 = blockIdx.y * 128, n0 = blockIdx.x * 128;

    float acc[8][8];
#pragma unroll
    for (int i = 0; i < 8; i++)
#pragma unroll
        for (int j = 0; j < 8; j++) acc[i][j] = 0.f;

    for (int k0 = 0; k0 < K; k0 += 16) {
#pragma unroll
        for (int q = 0; q < 2; q++) {            // A tile: 128 rows x 16 cols
            int f = tid * 2 + q;                 // 0..511
            int row = f >> 2;
            int col = (f & 3) * 4;
            float4 a = make_float4(0.f, 0.f, 0.f, 0.f);
            if (m0 + row < M)
                a = *(const float4*)(A + (size_t)(m0 + row) * K + k0 + col);
            As[col + 0][row] = a.x;
            As[col + 1][row] = a.y;
            As[col + 2][row] = a.z;
            As[col + 3][row] = a.w;
        }
#pragma unroll
        for (int q = 0; q < 2; q++) {            // B tile: 16 rows x 128 cols
            int f = tid * 2 + q;
            int row = f >> 5;
            int col = (f & 31) * 4;
            float4 bv = *(const float4*)(B + (size_t)(k0 + row) * Ncol + n0 + col);
            *(float4*)(&Bs[row][col]) = bv;
        }
        __syncthreads();
#pragma unroll
        for (int kk = 0; kk < 16; kk++) {
            float a[8], b[8];
            *(float4*)(a)     = *(const float4*)(&As[kk][ty * 8]);
            *(float4*)(a + 4) = *(const float4*)(&As[kk][ty * 8 + 4]);
            *(float4*)(b)     = *(const float4*)(&Bs[kk][tx * 8]);
            *(float4*)(b + 4) = *(const float4*)(&Bs[kk][tx * 8 + 4]);
#pragma unroll
            for (int i = 0; i < 8; i++)
#pragma unroll
                for (int j = 0; j < 8; j++) acc[i][j] += a[i] * b[j];
        }
        __syncthreads();
    }

#pragma unroll
    for (int i = 0; i < 8; i++) {
        int m = m0 + ty * 8 + i;
        if (m >= M) continue;
#pragma unroll
        for (int j = 0; j < 8; j++) {
            int n = n0 + tx * 8 + j;
            float v = acc[i][j];
            if (bias) v += bias[n];
            C[(size_t)m * Ncol + n] = v;
        }
    }
}

// ---------------- fused GATv2 layer 1 (block per node, online softmax) ----------------
// channels: ch = h*256 + tid, tid in [0,256)
__global__ __launch_bounds__(256) void k_gat1(const float* __restrict__ att,
                                              const float* __restrict__ bias)
{
    const int node = blockIdx.x;
    const int t = threadIdx.x;
    __shared__ float xr_s[D1];
    __shared__ float att_s[D1];
    __shared__ float warp_part[8][4];
    __shared__ float sm_m[4], sm_d[4], sm_s[4], sm_w[4];

#pragma unroll
    for (int h = 0; h < HH; h++) {
        int ch = h * C1 + t;
        xr_s[ch]  = g_xr1[(size_t)node * D1 + ch];
        att_s[ch] = att[ch];
    }
    if (t < 4) { sm_m[t] = -1e30f; sm_d[t] = 0.f; }
    __syncthreads();

    float acc[HH] = {0.f, 0.f, 0.f, 0.f};
    const int beg = g_offs[node], end = g_offs[node + 1];

    for (int k = beg; k < end; k++) {
        const int e = g_perm[k];
        const int src = g_src[e];
        float xlv[HH], p[HH];
#pragma unroll
        for (int h = 0; h < HH; h++) {
            int ch = h * C1 + t;
            float xl = g_xl1[(size_t)src * D1 + ch];
            float v = xl + xr_s[ch] + g_ef1[(size_t)e * D1 + ch];
            float lv = v > 0.f ? v : 0.2f * v;
            xlv[h] = xl;
            p[h] = att_s[ch] * lv;
        }
#pragma unroll
        for (int h = 0; h < HH; h++)
#pragma unroll
            for (int off = 16; off; off >>= 1)
                p[h] += __shfl_xor_sync(0xffffffffu, p[h], off);
        if ((t & 31) == 0) {
            int w = t >> 5;
#pragma unroll
            for (int h = 0; h < HH; h++) warp_part[w][h] = p[h];
        }
        __syncthreads();
        if (t < 4) {
            float l = 0.f;
#pragma unroll
            for (int w = 0; w < 8; w++) l += warp_part[w][t];
            float mo = sm_m[t];
            float mn = fmaxf(mo, l);
            float sc = __expf(mo - mn);
            float wv = __expf(l - mn);
            sm_d[t] = sm_d[t] * sc + wv;
            sm_m[t] = mn;
            sm_s[t] = sc;
            sm_w[t] = wv;
        }
        __syncthreads();
#pragma unroll
        for (int h = 0; h < HH; h++) acc[h] = acc[h] * sm_s[h] + sm_w[h] * xlv[h];
    }

#pragma unroll
    for (int h = 0; h < HH; h++) {
        int ch = h * C1 + t;
        float o = acc[h] / (sm_d[h] + 1e-16f);
        float v = o + bias[ch];
        g_h1[(size_t)node * D1 + ch] = fmaxf(v, 0.f);
    }
}

// ---------------- fused GATv2 layer 2 ----------------
// channel = tid, head = tid >> 6
__global__ __launch_bounds__(256) void k_gat2(const float* __restrict__ att,
                                              const float* __restrict__ bias)
{
    const int node = blockIdx.x;
    const int t = threadIdx.x;
    __shared__ float xr_s[D2];
    __shared__ float att_s[D2];
    __shared__ float warp_part[8];
    __shared__ float sm_m[4], sm_d[4], sm_s[4], sm_w[4];

    xr_s[t]  = g_xr2[(size_t)node * D2 + t];
    att_s[t] = att[t];
    if (t < 4) { sm_m[t] = -1e30f; sm_d[t] = 0.f; }
    __syncthreads();

    float acc = 0.f;
    const int h = t >> 6;
    const int beg = g_offs[node], end = g_offs[node + 1];

    for (int k = beg; k < end; k++) {
        const int e = g_perm[k];
        const int src = g_src[e];
        float xl = g_xl2[(size_t)src * D2 + t];
        float v = xl + xr_s[t] + g_ef2[(size_t)e * D2 + t];
        float lv = v > 0.f ? v : 0.2f * v;
        float p = att_s[t] * lv;
#pragma unroll
        for (int off = 16; off; off >>= 1)
            p += __shfl_xor_sync(0xffffffffu, p, off);
        if ((t & 31) == 0) warp_part[t >> 5] = p;
        __syncthreads();
        if (t < 4) {
            float l = warp_part[2 * t] + warp_part[2 * t + 1];
            float mo = sm_m[t];
            float mn = fmaxf(mo, l);
            float sc = __expf(mo - mn);
            float wv = __expf(l - mn);
            sm_d[t] = sm_d[t] * sc + wv;
            sm_m[t] = mn;
            sm_s[t] = sc;
            sm_w[t] = wv;
        }
        __syncthreads();
        acc = acc * sm_s[h] + sm_w[h] * xl;
    }

    float o = acc / (sm_d[h] + 1e-16f);
    g_h2[(size_t)node * D2 + t] = fmaxf(o + bias[t], 0.f);
}

// ---------------- MLP head (block per graph) ----------------
__global__ void k_mlp(const void* __restrict__ n_nodes,
                      const float* __restrict__ fc1w, const float* __restrict__ fc1b,
                      const float* __restrict__ fc2w, const float* __restrict__ fc2b,
                      float* __restrict__ out)
{
    const int b = blockIdx.x;
    const int t = threadIdx.x;  // 64 threads
    __shared__ float master[D2];
    __shared__ int s_last;
    __shared__ float ws[2];

    if (t == 0) {
        const int* w = (const int*)n_nodes;
        bool is64 = (w[1] == 0);
        long long cum = 0;
        if (is64) {
            const long long* l = (const long long*)n_nodes;
            for (int i = 0; i <= b; i++) cum += l[i];
        } else {
            for (int i = 0; i <= b; i++) cum += w[i];
        }
        s_last = (int)cum - 1;
    }
    __syncthreads();
    const int node = s_last;
    for (int i = t; i < D2; i += 64) master[i] = g_h2[(size_t)node * D2 + i];
    __syncthreads();

    float z = fc1b[t];
    for (int c = 0; c < D2; c++) z += master[c] * fc1w[c * 64 + t];
    z = fmaxf(z, 0.f);
    float v = z * fc2w[t];
#pragma unroll
    for (int off = 16; off; off >>= 1) v += __shfl_xor_sync(0xffffffffu, v, off);
    if ((t & 31) == 0) ws[t >> 5] = v;
    __syncthreads();
    if (t == 0) out[b] = ws[0] + ws[1] + fc2b[0];
}

// ---------------- launch ----------------
extern "C" void kernel_launch(void* const* d_in, const int* in_sizes, int n_in,
                              void* d_out, int out_size)
{
    const float* x    = (const float*)d_in[0];
    const void*  ei   = d_in[1];
    const float* ea   = (const float*)d_in[2];
    const void*  nnod = d_in[3];
    const float* Wl1  = (const float*)d_in[4];
    const float* bl1  = (const float*)d_in[5];
    const float* Wr1  = (const float*)d_in[6];
    const float* br1  = (const float*)d_in[7];
    const float* We1  = (const float*)d_in[8];
    const float* att1 = (const float*)d_in[9];
    const float* b1   = (const float*)d_in[10];
    const float* Wl2  = (const float*)d_in[11];
    const float* bl2  = (const float*)d_in[12];
    const float* Wr2  = (const float*)d_in[13];
    const float* br2  = (const float*)d_in[14];
    const float* We2  = (const float*)d_in[15];
    const float* att2 = (const float*)d_in[16];
    const float* b2   = (const float*)d_in[17];
    const float* fc1w = (const float*)d_in[18];
    const float* fc1b = (const float*)d_in[19];
    const float* fc2w = (const float*)d_in[20];
    const float* fc2b = (const float*)d_in[21];
    float* out = (float*)d_out;

    float *xl1, *xr1, *ef1, *h1, *xl2, *xr2, *ef2;
    cudaGetSymbolAddress((void**)&xl1, g_xl1);
    cudaGetSymbolAddress((void**)&xr1, g_xr1);
    cudaGetSymbolAddress((void**)&ef1, g_ef1);
    cudaGetSymbolAddress((void**)&h1,  g_h1);
    cudaGetSymbolAddress((void**)&xl2, g_xl2);
    cudaGetSymbolAddress((void**)&xr2, g_xr2);
    cudaGetSymbolAddress((void**)&ef2, g_ef2);

    const int TB = 256;
    // CSR build
    k_zero<<<(NN + TB - 1) / TB, TB>>>();
    k_convert<<<(EE + TB - 1) / TB, TB>>>(ei);
    k_count<<<(EE + TB - 1) / TB, TB>>>();
    k_scan<<<1, 1024>>>();
    k_scatter<<<(EE + TB - 1) / TB, TB>>>();

    // layer 1 projections
    {
        dim3 g1(D1 / 128, (NN + 127) / 128);
        k_gemm<<<g1, 256>>>(x, Wl1, bl1, xl1, NN, 128, D1);
        k_gemm<<<g1, 256>>>(x, Wr1, br1, xr1, NN, 128, D1);
        dim3 ge(D1 / 128, (EE + 127) / 128);
        k_gemm<<<ge, 256>>>(ea, We1, nullptr, ef1, EE, 16, D1);
    }
    k_gat1<<<NN, 256>>>(att1, b1);

    // layer 2 projections
    {
        dim3 g2(D2 / 128, (NN + 127) / 128);
        k_gemm<<<g2, 256>>>(h1, Wl2, bl2, xl2, NN, D1, D2);
        k_gemm<<<g2, 256>>>(h1, Wr2, br2, xr2, NN, D1, D2);
        dim3 ge(D2 / 128, (EE + 127) / 128);
        k_gemm<<<ge, 256>>>(ea, We2, nullptr, ef2, EE, 16, D2);
    }
    k_gat2<<<NN, 256>>>(att2, b2);

    k_mlp<<<BB, 64>>>(nnod, fc1w, fc1b, fc2w, fc2b, out);
}

// round 2
// speedup vs baseline: 2.9835x; 2.9835x over previous
#include <cuda_runtime.h>
#include <cuda_bf16.h>
#include <math.h>

#define NN 49920
#define EE 200000
#define BB 128
#define C1 256
#define C2 64
#define HH 4
#define D1 1024
#define D2 256
#define NB ((NN + 255) / 256)   // 195

// ---------------- scratch ----------------
__device__ float g_xl1[(size_t)NN * D1];
__device__ float g_xr1[(size_t)NN * D1];
__device__ float g_ef1[(size_t)EE * D1];
__device__ float g_h1 [(size_t)NN * D1];
__device__ float g_xl2[(size_t)NN * D2];
__device__ float g_xr2[(size_t)NN * D2];
__device__ float g_ef2[(size_t)EE * D2];
__device__ float g_h2 [(size_t)NN * D2];

__device__ int g_src[EE];
__device__ int g_dst[EE];
__device__ int g_cnt[NN];
__device__ int g_cur[NN];
__device__ int g_offs[NN + 1];
__device__ int g_perm[EE];
__device__ int g_part[256];

// ---------------- CSR build ----------------
__global__ void k_zero()
{
    int i = blockIdx.x * blockDim.x + threadIdx.x;
    if (i < NN) { g_cnt[i] = 0; g_cur[i] = 0; }
}

__global__ void k_convert(const void* __restrict__ ei)
{
    int e = blockIdx.x * blockDim.x + threadIdx.x;
    if (e >= EE) return;
    const int* w = (const int*)ei;
    bool is64 = true;
#pragma unroll
    for (int i = 1; i < 16; i += 2) is64 = is64 && (w[i] == 0);
    if (is64) {
        const long long* l = (const long long*)ei;
        g_src[e] = (int)l[e];
        g_dst[e] = (int)l[(size_t)EE + e];
    } else {
        g_src[e] = w[e];
        g_dst[e] = w[EE + e];
    }
}

__global__ void k_count()
{
    int e = blockIdx.x * blockDim.x + threadIdx.x;
    if (e < EE) atomicAdd(&g_cnt[g_dst[e]], 1);
}

__global__ void k_scanA()
{
    __shared__ int sw[8];
    int t = threadIdx.x;
    int i = blockIdx.x * 256 + t;
    int v = (i < NN) ? g_cnt[i] : 0;
#pragma unroll
    for (int off = 16; off; off >>= 1) v += __shfl_xor_sync(0xffffffffu, v, off);
    if ((t & 31) == 0) sw[t >> 5] = v;
    __syncthreads();
    if (t == 0) {
        int s = 0;
#pragma unroll
        for (int j = 0; j < 8; j++) s += sw[j];
        g_part[blockIdx.x] = s;
    }
}

__global__ void k_scanB()
{
    __shared__ int s[256];
    int t = threadIdx.x;
    int v = (t < NB) ? g_part[t] : 0;
    s[t] = v;
    __syncthreads();
    for (int off = 1; off < 256; off <<= 1) {
        int add = (t >= off) ? s[t - off] : 0;
        __syncthreads();
        s[t] += add;
        __syncthreads();
    }
    g_part[t] = s[t] - v;   // exclusive
}

__global__ void k_scanC()
{
    __shared__ int s[256];
    int t = threadIdx.x;
    int i = blockIdx.x * 256 + t;
    int v = (i < NN) ? g_cnt[i] : 0;
    s[t] = v;
    __syncthreads();
    for (int off = 1; off < 256; off <<= 1) {
        int add = (t >= off) ? s[t - off] : 0;
        __syncthreads();
        s[t] += add;
        __syncthreads();
    }
    if (i < NN) g_offs[i] = g_part[blockIdx.x] + s[t] - v;
    if (i == NN - 1) g_offs[NN] = EE;
}

__global__ void k_scatter()
{
    int e = blockIdx.x * blockDim.x + threadIdx.x;
    if (e >= EE) return;
    int d = g_dst[e];
    int p = g_offs[d] + atomicAdd(&g_cur[d], 1);
    g_perm[p] = e;
}

// ---------------- bf16x3 tensor-core GEMM ----------------
// C[M,N] = A[M,K] @ B[K,N] (+bias). fp32 in/out, internal bf16 split:
// A = Ah + Al, B = Bh + Bl; C ≈ AhBh + AlBh + AhBl (AlBl dropped, ~2^-16).
// BM=BN=128, BK=32. 256 threads (8 warps, 4x2), warp tile 32x64.
#define AST 40    // A smem row stride (bf16) — conflict-free ldmatrix
#define BST 136   // B smem row stride (bf16)

__device__ __forceinline__ unsigned sptr(const void* p)
{
    return (unsigned)__cvta_generic_to_shared(p);
}
__device__ __forceinline__ void ldsm_x4(unsigned* r, unsigned a)
{
    asm volatile("ldmatrix.sync.aligned.m8n8.x4.shared.b16 {%0,%1,%2,%3}, [%4];\n"
                 : "=r"(r[0]), "=r"(r[1]), "=r"(r[2]), "=r"(r[3]) : "r"(a));
}
__device__ __forceinline__ void ldsm_x2t(unsigned* r, unsigned a)
{
    asm volatile("ldmatrix.sync.aligned.m8n8.x2.trans.shared.b16 {%0,%1}, [%2];\n"
                 : "=r"(r[0]), "=r"(r[1]) : "r"(a));
}
__device__ __forceinline__ void mma16816(float* d, const unsigned* a, const unsigned* b)
{
    asm volatile(
        "mma.sync.aligned.m16n8k16.row.col.f32.bf16.bf16.f32 "
        "{%0,%1,%2,%3}, {%4,%5,%6,%7}, {%8,%9}, {%0,%1,%2,%3};\n"
        : "+f"(d[0]), "+f"(d[1]), "+f"(d[2]), "+f"(d[3])
        : "r"(a[0]), "r"(a[1]), "r"(a[2]), "r"(a[3]), "r"(b[0]), "r"(b[1]));
}

__global__ __launch_bounds__(256) void k_gemm_mma(const float* __restrict__ A,
                                                  const float* __restrict__ B,
                                                  const float* __restrict__ bias,
                                                  float* __restrict__ C,
                                                  int M, int K, int Ncol)
{
    __shared__ __nv_bfloat16 Ah[128 * AST], Al[128 * AST];
    __shared__ __nv_bfloat16 Bh[32 * BST],  Bl[32 * BST];

    const int tid = threadIdx.x;
    const int lane = tid & 31, w = tid >> 5;
    const int wm = w & 3, wn = w >> 2;
    const int m0 = blockIdx.y * 128, n0 = blockIdx.x * 128;

    float acc[2][8][4];
#pragma unroll
    for (int i = 0; i < 2; i++)
#pragma unroll
        for (int j = 0; j < 8; j++)
#pragma unroll
            for (int r = 0; r < 4; r++) acc[i][j][r] = 0.f;

    for (int k0 = 0; k0 < K; k0 += 32) {
        // stage A: 128 rows x 32 cols
#pragma unroll
        for (int q = 0; q < 4; q++) {
            int f = tid + q * 256;
            int row = f >> 3, kc = (f & 7) * 4;
            float4 v = make_float4(0.f, 0.f, 0.f, 0.f);
            if (m0 + row < M && k0 + kc < K)
                v = *(const float4*)(A + (size_t)(m0 + row) * K + k0 + kc);
            __nv_bfloat162 h0 = __float22bfloat162_rn(make_float2(v.x, v.y));
            __nv_bfloat162 h1 = __float22bfloat162_rn(make_float2(v.z, v.w));
            __nv_bfloat162 l0 = __float22bfloat162_rn(make_float2(
                v.x - __bfloat162float(h0.x), v.y - __bfloat162float(h0.y)));
            __nv_bfloat162 l1 = __float22bfloat162_rn(make_float2(
                v.z - __bfloat162float(h1.x), v.w - __bfloat162float(h1.y)));
            *(uint2*)&Ah[row * AST + kc] = make_uint2(*(unsigned*)&h0, *(unsigned*)&h1);
            *(uint2*)&Al[row * AST + kc] = make_uint2(*(unsigned*)&l0, *(unsigned*)&l1);
        }
        // stage B: 32 rows x 128 cols
#pragma unroll
        for (int q = 0; q < 4; q++) {
            int f = tid + q * 256;
            int row = f >> 5, nc = (f & 31) * 4;
            float4 v = make_float4(0.f, 0.f, 0.f, 0.f);
            if (k0 + row < K)
                v = *(const float4*)(B + (size_t)(k0 + row) * Ncol + n0 + nc);
            __nv_bfloat162 h0 = __float22bfloat162_rn(make_float2(v.x, v.y));
            __nv_bfloat162 h1 = __float22bfloat162_rn(make_float2(v.z, v.w));
            __nv_bfloat162 l0 = __float22bfloat162_rn(make_float2(
                v.x - __bfloat162float(h0.x), v.y - __bfloat162float(h0.y)));
            __nv_bfloat162 l1 = __float22bfloat162_rn(make_float2(
                v.z - __bfloat162float(h1.x), v.w - __bfloat162float(h1.y)));
            *(uint2*)&Bh[row * BST + nc] = make_uint2(*(unsigned*)&h0, *(unsigned*)&h1);
            *(uint2*)&Bl[row * BST + nc] = make_uint2(*(unsigned*)&l0, *(unsigned*)&l1);
        }
        __syncthreads();

#pragma unroll
        for (int ks = 0; ks < 32; ks += 16) {
            unsigned aFh[2][4], aFl[2][4];
#pragma unroll
            for (int mt = 0; mt < 2; mt++) {
                int row = wm * 32 + mt * 16 + (lane & 7) + ((lane >> 3) & 1) * 8;
                int col = ks + (lane >> 4) * 8;
                ldsm_x4(aFh[mt], sptr(&Ah[row * AST + col]));
                ldsm_x4(aFl[mt], sptr(&Al[row * AST + col]));
            }
#pragma unroll
            for (int nt = 0; nt < 8; nt++) {
                int brow = ks + (lane & 15);
                int bcol = wn * 64 + nt * 8;
                unsigned bFh[2], bFl[2];
                ldsm_x2t(bFh, sptr(&Bh[brow * BST + bcol]));
                ldsm_x2t(bFl, sptr(&Bl[brow * BST + bcol]));
#pragma unroll
                for (int mt = 0; mt < 2; mt++) {
                    mma16816(acc[mt][nt], aFh[mt], bFh);
                    mma16816(acc[mt][nt], aFl[mt], bFh);
                    mma16816(acc[mt][nt], aFh[mt], bFl);
                }
            }
        }
        __syncthreads();
    }

    // epilogue
#pragma unroll
    for (int mt = 0; mt < 2; mt++) {
#pragma unroll
        for (int nt = 0; nt < 8; nt++) {
            int r = m0 + wm * 32 + mt * 16 + (lane >> 2);
            int c = n0 + wn * 64 + nt * 8 + (lane & 3) * 2;
            float b0 = 0.f, b1 = 0.f;
            if (bias) { b0 = __ldg(bias + c); b1 = __ldg(bias + c + 1); }
            if (r < M)
                *(float2*)(C + (size_t)r * Ncol + c) =
                    make_float2(acc[mt][nt][0] + b0, acc[mt][nt][1] + b1);
            if (r + 8 < M)
                *(float2*)(C + (size_t)(r + 8) * Ncol + c) =
                    make_float2(acc[mt][nt][2] + b0, acc[mt][nt][3] + b1);
        }
    }
}

// ---------------- fused GATv2 layer 1 ----------------
__global__ __launch_bounds__(256) void k_gat1(const float* __restrict__ att,
                                              const float* __restrict__ bias)
{
    const int node = blockIdx.x;
    const int t = threadIdx.x;
    __shared__ float xr_s[D1];
    __shared__ float att_s[D1];
    __shared__ float warp_part[8][4];
    __shared__ float sm_m[4], sm_d[4], sm_s[4], sm_w[4];

#pragma unroll
    for (int h = 0; h < HH; h++) {
        int ch = h * C1 + t;
        xr_s[ch]  = g_xr1[(size_t)node * D1 + ch];
        att_s[ch] = att[ch];
    }
    if (t < 4) { sm_m[t] = -1e30f; sm_d[t] = 0.f; }
    __syncthreads();

    float acc[HH] = {0.f, 0.f, 0.f, 0.f};
    const int beg = g_offs[node], end = g_offs[node + 1];

    for (int k = beg; k < end; k++) {
        const int e = g_perm[k];
        const int src = g_src[e];
        float xlv[HH], p[HH];
#pragma unroll
        for (int h = 0; h < HH; h++) {
            int ch = h * C1 + t;
            float xl = g_xl1[(size_t)src * D1 + ch];
            float v = xl + xr_s[ch] + g_ef1[(size_t)e * D1 + ch];
            float lv = v > 0.f ? v : 0.2f * v;
            xlv[h] = xl;
            p[h] = att_s[ch] * lv;
        }
#pragma unroll
        for (int h = 0; h < HH; h++)
#pragma unroll
            for (int off = 16; off; off >>= 1)
                p[h] += __shfl_xor_sync(0xffffffffu, p[h], off);
        if ((t & 31) == 0) {
            int w = t >> 5;
#pragma unroll
            for (int h = 0; h < HH; h++) warp_part[w][h] = p[h];
        }
        __syncthreads();
        if (t < 4) {
            float l = 0.f;
#pragma unroll
            for (int w = 0; w < 8; w++) l += warp_part[w][t];
            float mo = sm_m[t];
            float mn = fmaxf(mo, l);
            float sc = __expf(mo - mn);
            float wv = __expf(l - mn);
            sm_d[t] = sm_d[t] * sc + wv;
            sm_m[t] = mn;
            sm_s[t] = sc;
            sm_w[t] = wv;
        }
        __syncthreads();
#pragma unroll
        for (int h = 0; h < HH; h++) acc[h] = acc[h] * sm_s[h] + sm_w[h] * xlv[h];
    }

#pragma unroll
    for (int h = 0; h < HH; h++) {
        int ch = h * C1 + t;
        float o = acc[h] / (sm_d[h] + 1e-16f);
        float v = o + bias[ch];
        g_h1[(size_t)node * D1 + ch] = fmaxf(v, 0.f);
    }
}

// ---------------- fused GATv2 layer 2 ----------------
__global__ __launch_bounds__(256) void k_gat2(const float* __restrict__ att,
                                              const float* __restrict__ bias)
{
    const int node = blockIdx.x;
    const int t = threadIdx.x;
    __shared__ float xr_s[D2];
    __shared__ float att_s[D2];
    __shared__ float warp_part[8];
    __shared__ float sm_m[4], sm_d[4], sm_s[4], sm_w[4];

    xr_s[t]  = g_xr2[(size_t)node * D2 + t];
    att_s[t] = att[t];
    if (t < 4) { sm_m[t] = -1e30f; sm_d[t] = 0.f; }
    __syncthreads();

    float acc = 0.f;
    const int h = t >> 6;
    const int beg = g_offs[node], end = g_offs[node + 1];

    for (int k = beg; k < end; k++) {
        const int e = g_perm[k];
        const int src = g_src[e];
        float xl = g_xl2[(size_t)src * D2 + t];
        float v = xl + xr_s[t] + g_ef2[(size_t)e * D2 + t];
        float lv = v > 0.f ? v : 0.2f * v;
        float p = att_s[t] * lv;
#pragma unroll
        for (int off = 16; off; off >>= 1)
            p += __shfl_xor_sync(0xffffffffu, p, off);
        if ((t & 31) == 0) warp_part[t >> 5] = p;
        __syncthreads();
        if (t < 4) {
            float l = warp_part[2 * t] + warp_part[2 * t + 1];
            float mo = sm_m[t];
            float mn = fmaxf(mo, l);
            float sc = __expf(mo - mn);
            float wv = __expf(l - mn);
            sm_d[t] = sm_d[t] * sc + wv;
            sm_m[t] = mn;
            sm_s[t] = sc;
            sm_w[t] = wv;
        }
        __syncthreads();
        acc = acc * sm_s[h] + sm_w[h] * xl;
    }

    float o = acc / (sm_d[h] + 1e-16f);
    g_h2[(size_t)node * D2 + t] = fmaxf(o + bias[t], 0.f);
}

// ---------------- MLP head ----------------
__global__ void k_mlp(const void* __restrict__ n_nodes,
                      const float* __restrict__ fc1w, const float* __restrict__ fc1b,
                      const float* __restrict__ fc2w, const float* __restrict__ fc2b,
                      float* __restrict__ out)
{
    const int b = blockIdx.x;
    const int t = threadIdx.x;  // 64
    __shared__ float master[D2];
    __shared__ int s_last;
    __shared__ float ws[2];

    if (t == 0) {
        const int* w = (const int*)n_nodes;
        bool is64 = (w[1] == 0);
        long long cum = 0;
        if (is64) {
            const long long* l = (const long long*)n_nodes;
            for (int i = 0; i <= b; i++) cum += l[i];
        } else {
            for (int i = 0; i <= b; i++) cum += w[i];
        }
        s_last = (int)cum - 1;
    }
    __syncthreads();
    const int node = s_last;
    for (int i = t; i < D2; i += 64) master[i] = g_h2[(size_t)node * D2 + i];
    __syncthreads();

    float z = fc1b[t];
    for (int c = 0; c < D2; c++) z += master[c] * fc1w[c * 64 + t];
    z = fmaxf(z, 0.f);
    float v = z * fc2w[t];
#pragma unroll
    for (int off = 16; off; off >>= 1) v += __shfl_xor_sync(0xffffffffu, v, off);
    if ((t & 31) == 0) ws[t >> 5] = v;
    __syncthreads();
    if (t == 0) out[b] = ws[0] + ws[1] + fc2b[0];
}

// ---------------- launch ----------------
extern "C" void kernel_launch(void* const* d_in, const int* in_sizes, int n_in,
                              void* d_out, int out_size)
{
    const float* x    = (const float*)d_in[0];
    const void*  ei   = d_in[1];
    const float* ea   = (const float*)d_in[2];
    const void*  nnod = d_in[3];
    const float* Wl1  = (const float*)d_in[4];
    const float* bl1  = (const float*)d_in[5];
    const float* Wr1  = (const float*)d_in[6];
    const float* br1  = (const float*)d_in[7];
    const float* We1  = (const float*)d_in[8];
    const float* att1 = (const float*)d_in[9];
    const float* b1   = (const float*)d_in[10];
    const float* Wl2  = (const float*)d_in[11];
    const float* bl2  = (const float*)d_in[12];
    const float* Wr2  = (const float*)d_in[13];
    const float* br2  = (const float*)d_in[14];
    const float* We2  = (const float*)d_in[15];
    const float* att2 = (const float*)d_in[16];
    const float* b2   = (const float*)d_in[17];
    const float* fc1w = (const float*)d_in[18];
    const float* fc1b = (const float*)d_in[19];
    const float* fc2w = (const float*)d_in[20];
    const float* fc2b = (const float*)d_in[21];
    float* out = (float*)d_out;

    float *xl1, *xr1, *ef1, *h1, *xl2, *xr2, *ef2;
    cudaGetSymbolAddress((void**)&xl1, g_xl1);
    cudaGetSymbolAddress((void**)&xr1, g_xr1);
    cudaGetSymbolAddress((void**)&ef1, g_ef1);
    cudaGetSymbolAddress((void**)&h1,  g_h1);
    cudaGetSymbolAddress((void**)&xl2, g_xl2);
    cudaGetSymbolAddress((void**)&xr2, g_xr2);
    cudaGetSymbolAddress((void**)&ef2, g_ef2);

    const int TB = 256;
    k_zero<<<(NN + TB - 1) / TB, TB>>>();
    k_convert<<<(EE + TB - 1) / TB, TB>>>(ei);
    k_count<<<(EE + TB - 1) / TB, TB>>>();
    k_scanA<<<NB, 256>>>();
    k_scanB<<<1, 256>>>();
    k_scanC<<<NB, 256>>>();
    k_scatter<<<(EE + TB - 1) / TB, TB>>>();

    // layer 1 projections (tensor cores)
    {
        dim3 g1(D1 / 128, NN / 128);
        k_gemm_mma<<<g1, 256>>>(x, Wl1, bl1, xl1, NN, 128, D1);
        k_gemm_mma<<<g1, 256>>>(x, Wr1, br1, xr1, NN, 128, D1);
        dim3 ge(D1 / 128, (EE + 127) / 128);
        k_gemm_mma<<<ge, 256>>>(ea, We1, nullptr, ef1, EE, 16, D1);
    }
    k_gat1<<<NN, 256>>>(att1, b1);

    // layer 2 projections
    {
        dim3 g2(D2 / 128, NN / 128);
        k_gemm_mma<<<g2, 256>>>(h1, Wl2, bl2, xl2, NN, D1, D2);
        k_gemm_mma<<<g2, 256>>>(h1, Wr2, br2, xr2, NN, D1, D2);
        dim3 ge(D2 / 128, (EE + 127) / 128);
        k_gemm_mma<<<ge, 256>>>(ea, We2, nullptr, ef2, EE, 16, D2);
    }
    k_gat2<<<NN, 256>>>(att2, b2);

    k_mlp<<<BB, 64>>>(nnod, fc1w, fc1b, fc2w, fc2b, out);
}

// round 4
// speedup vs baseline: 3.3592x; 1.1259x over previous
#include <cuda_runtime.h>
#include <cuda_bf16.h>
#include <math.h>

#define NN 49920
#define EE 200000
#define BB 128
#define C1 256
#define C2 64
#define HH 4
#define D1 1024
#define D2 256
#define NB ((NN + 255) / 256)   // 195

typedef __nv_bfloat16 bf16;

// ---------------- scratch ----------------
__device__ float g_xl1[(size_t)NN * D1];
__device__ float g_xr1[(size_t)NN * D1];
__device__ float g_ef1[(size_t)EE * D1];
__device__ float g_xl2[(size_t)NN * D2];
__device__ float g_xr2[(size_t)NN * D2];
__device__ float g_ef2[(size_t)EE * D2];
__device__ float g_h2 [(size_t)NN * D2];

// bf16 hi/lo split operands
__device__ bf16 g_xh [(size_t)NN * 128],  g_xlo[(size_t)NN * 128];
__device__ bf16 g_eah[(size_t)EE * 16],   g_eal[(size_t)EE * 16];
__device__ bf16 g_h1h[(size_t)NN * D1],   g_h1l[(size_t)NN * D1];
__device__ bf16 g_wl1h[128 * 1024], g_wl1l[128 * 1024];
__device__ bf16 g_wr1h[128 * 1024], g_wr1l[128 * 1024];
__device__ bf16 g_we1h[16 * 1024],  g_we1l[16 * 1024];
__device__ bf16 g_wl2h[1024 * 256], g_wl2l[1024 * 256];
__device__ bf16 g_wr2h[1024 * 256], g_wr2l[1024 * 256];
__device__ bf16 g_we2h[16 * 256],   g_we2l[16 * 256];

__device__ int g_src[EE];
__device__ int g_dst[EE];
__device__ int g_cnt[NN];
__device__ int g_cur[NN];
__device__ int g_offs[NN + 1];
__device__ int g_perm[EE];
__device__ int g_part[256];

// ---------------- CSR build ----------------
__global__ void k_zero()
{
    int i = blockIdx.x * blockDim.x + threadIdx.x;
    if (i < NN) { g_cnt[i] = 0; g_cur[i] = 0; }
}

__global__ void k_convert(const void* __restrict__ ei)
{
    int e = blockIdx.x * blockDim.x + threadIdx.x;
    if (e >= EE) return;
    const int* w = (const int*)ei;
    bool is64 = true;
#pragma unroll
    for (int i = 1; i < 16; i += 2) is64 = is64 && (w[i] == 0);
    if (is64) {
        const long long* l = (const long long*)ei;
        g_src[e] = (int)l[e];
        g_dst[e] = (int)l[(size_t)EE + e];
    } else {
        g_src[e] = w[e];
        g_dst[e] = w[EE + e];
    }
}

__global__ void k_count()
{
    int e = blockIdx.x * blockDim.x + threadIdx.x;
    if (e < EE) atomicAdd(&g_cnt[g_dst[e]], 1);
}

__global__ void k_scanA()
{
    __shared__ int sw[8];
    int t = threadIdx.x;
    int i = blockIdx.x * 256 + t;
    int v = (i < NN) ? g_cnt[i] : 0;
#pragma unroll
    for (int off = 16; off; off >>= 1) v += __shfl_xor_sync(0xffffffffu, v, off);
    if ((t & 31) == 0) sw[t >> 5] = v;
    __syncthreads();
    if (t == 0) {
        int s = 0;
#pragma unroll
        for (int j = 0; j < 8; j++) s += sw[j];
        g_part[blockIdx.x] = s;
    }
}

__global__ void k_scanB()
{
    __shared__ int s[256];
    int t = threadIdx.x;
    int v = (t < NB) ? g_part[t] : 0;
    s[t] = v;
    __syncthreads();
    for (int off = 1; off < 256; off <<= 1) {
        int add = (t >= off) ? s[t - off] : 0;
        __syncthreads();
        s[t] += add;
        __syncthreads();
    }
    g_part[t] = s[t] - v;
}

__global__ void k_scanC()
{
    __shared__ int s[256];
    int t = threadIdx.x;
    int i = blockIdx.x * 256 + t;
    int v = (i < NN) ? g_cnt[i] : 0;
    s[t] = v;
    __syncthreads();
    for (int off = 1; off < 256; off <<= 1) {
        int add = (t >= off) ? s[t - off] : 0;
        __syncthreads();
        s[t] += add;
        __syncthreads();
    }
    if (i < NN) g_offs[i] = g_part[blockIdx.x] + s[t] - v;
    if (i == NN - 1) g_offs[NN] = EE;
}

__global__ void k_scatter()
{
    int e = blockIdx.x * blockDim.x + threadIdx.x;
    if (e >= EE) return;
    int d = g_dst[e];
    int p = g_offs[d] + atomicAdd(&g_cur[d], 1);
    g_perm[p] = e;
}

// ---------------- bf16 hi/lo split ----------------
__global__ void k_split(const float* __restrict__ src, bf16* __restrict__ hi,
                        bf16* __restrict__ lo, int n)
{
    int i = blockIdx.x * blockDim.x + threadIdx.x;
    if (i >= n) return;
    float v = src[i];
    bf16 h = __float2bfloat16_rn(v);
    hi[i] = h;
    lo[i] = __float2bfloat16_rn(v - __bfloat162float(h));
}

// ---------------- bf16x3 tensor-core GEMM, cp.async double-buffered ----------------
// C = A@B (+bias); A,B given as bf16 (hi,lo) pairs; C ~= AhBh + AlBh + AhBl.
// BM=BN=128, BK=32. 128 threads, 4 warps (2x2), warp tile 64x64.
#define AST 40    // A smem row stride (bf16)
#define BST 136   // B smem row stride (bf16)
#define A_HALF (128 * AST)       // one (h or l) A tile, bf16 elems
#define B_HALF (32 * BST)
#define STAGE_ELEMS (2 * A_HALF + 2 * B_HALF)
#define SMEM_BYTES (2 * STAGE_ELEMS * 2)

__device__ __forceinline__ void cpa16(unsigned dst, const void* src, int sz)
{
    asm volatile("cp.async.cg.shared.global [%0], [%1], 16, %2;\n"
                 :: "r"(dst), "l"(src), "r"(sz));
}
__device__ __forceinline__ void ldsm_x4(unsigned* r, unsigned a)
{
    asm volatile("ldmatrix.sync.aligned.m8n8.x4.shared.b16 {%0,%1,%2,%3}, [%4];\n"
                 : "=r"(r[0]), "=r"(r[1]), "=r"(r[2]), "=r"(r[3]) : "r"(a));
}
__device__ __forceinline__ void ldsm_x2t(unsigned* r, unsigned a)
{
    asm volatile("ldmatrix.sync.aligned.m8n8.x2.trans.shared.b16 {%0,%1}, [%2];\n"
                 : "=r"(r[0]), "=r"(r[1]) : "r"(a));
}
__device__ __forceinline__ void mma16816(float* d, const unsigned* a, const unsigned* b)
{
    asm volatile(
        "mma.sync.aligned.m16n8k16.row.col.f32.bf16.bf16.f32 "
        "{%0,%1,%2,%3}, {%4,%5,%6,%7}, {%8,%9}, {%0,%1,%2,%3};\n"
        : "+f"(d[0]), "+f"(d[1]), "+f"(d[2]), "+f"(d[3])
        : "r"(a[0]), "r"(a[1]), "r"(a[2]), "r"(a[3]), "r"(b[0]), "r"(b[1]));
}

template <typename OutT>
__global__ __launch_bounds__(128, 2) void k_gemm_bf3(const bf16* __restrict__ Ah,
                                                     const bf16* __restrict__ Al,
                                                     const bf16* __restrict__ Bh,
                                                     const bf16* __restrict__ Bl,
                                                     const float* __restrict__ bias,
                                                     OutT* __restrict__ C,
                                                     int M, int K, int Ncol)
{
    extern __shared__ bf16 smem[];
    // stage layout: [Ah_s | Al_s | Bh_s | Bl_s]
    const int tid = threadIdx.x;
    const int lane = tid & 31, w = tid >> 5;
    const int wm = w & 1, wn = w >> 1;
    const int m0 = blockIdx.y * 128, n0 = blockIdx.x * 128;
    const int r4 = lane >> 2, c4 = lane & 3;

    float acc[4][8][4];
#pragma unroll
    for (int i = 0; i < 4; i++)
#pragma unroll
        for (int j = 0; j < 8; j++)
#pragma unroll
            for (int r = 0; r < 4; r++) acc[i][j][r] = 0.f;

    const int T = (K + 31) / 32;

    auto load_stage = [&](int it) {
        const int k0 = it * 32;
        bf16* S = smem + (it & 1) * STAGE_ELEMS;
        // A: 2 parts x 128 rows x 4 chunks(16B = 8 bf16)
#pragma unroll
        for (int q = 0; q < 8; q++) {
            int f = tid + q * 128;              // 0..1023
            int hl = f >> 9;
            int r = (f >> 2) & 127;
            int ck = (f & 3) * 8;
            const bf16* src = hl ? Al : Ah;
            bool ok = (m0 + r < M) && (k0 + ck < K);
            const bf16* sp = ok ? (src + (size_t)(m0 + r) * K + k0 + ck) : src;
            bf16* dp = S + hl * A_HALF + r * AST + ck;
            cpa16((unsigned)__cvta_generic_to_shared(dp), sp, ok ? 16 : 0);
        }
        // B: 2 parts x 32 rows x 16 chunks
#pragma unroll
        for (int q = 0; q < 8; q++) {
            int f = tid + q * 128;
            int hl = f >> 9;
            int r = (f >> 4) & 31;
            int cn = (f & 15) * 8;
            const bf16* src = hl ? Bl : Bh;
            bool ok = (k0 + r < K);
            const bf16* sp = ok ? (src + (size_t)(k0 + r) * Ncol + n0 + cn) : src;
            bf16* dp = S + 2 * A_HALF + hl * B_HALF + r * BST + cn;
            cpa16((unsigned)__cvta_generic_to_shared(dp), sp, ok ? 16 : 0);
        }
        asm volatile("cp.async.commit_group;\n");
    };

    load_stage(0);

    for (int it = 0; it < T; it++) {
        if (it + 1 < T) {
            load_stage(it + 1);
            asm volatile("cp.async.wait_group 1;\n");
        } else {
            asm volatile("cp.async.wait_group 0;\n");
        }
        __syncthreads();

        const bf16* S = smem + (it & 1) * STAGE_ELEMS;
        const bf16* sAh = S;
        const bf16* sAl = S + A_HALF;
        const bf16* sBh = S + 2 * A_HALF;
        const bf16* sBl = S + 2 * A_HALF + B_HALF;

#pragma unroll
        for (int ks = 0; ks < 32; ks += 16) {
            unsigned aFh[4][4], aFl[4][4];
#pragma unroll
            for (int mt = 0; mt < 4; mt++) {
                int row = wm * 64 + mt * 16 + (lane & 7) + ((lane >> 3) & 1) * 8;
                int col = ks + (lane >> 4) * 8;
                ldsm_x4(aFh[mt], (unsigned)__cvta_generic_to_shared(sAh + row * AST + col));
                ldsm_x4(aFl[mt], (unsigned)__cvta_generic_to_shared(sAl + row * AST + col));
            }
#pragma unroll
            for (int nt = 0; nt < 8; nt++) {
                int brow = ks + (lane & 15);
                int bcol = wn * 64 + nt * 8;
                unsigned bFh[2], bFl[2];
                ldsm_x2t(bFh, (unsigned)__cvta_generic_to_shared(sBh + brow * BST + bcol));
                ldsm_x2t(bFl, (unsigned)__cvta_generic_to_shared(sBl + brow * BST + bcol));
#pragma unroll
                for (int mt = 0; mt < 4; mt++) {
                    mma16816(acc[mt][nt], aFh[mt], bFh);
                    mma16816(acc[mt][nt], aFl[mt], bFh);
                    mma16816(acc[mt][nt], aFh[mt], bFl);
                }
            }
        }
        __syncthreads();
    }

    // epilogue
#pragma unroll
    for (int mt = 0; mt < 4; mt++) {
#pragma unroll
        for (int nt = 0; nt < 8; nt++) {
            int r = m0 + wm * 64 + mt * 16 + r4;
            int c = n0 + wn * 64 + nt * 8 + c4 * 2;
            float b0 = 0.f, b1 = 0.f;
            if (bias) { b0 = __ldg(bias + c); b1 = __ldg(bias + c + 1); }
            float* Cf = (float*)C;
            if (r < M)
                *(float2*)(Cf + (size_t)r * Ncol + c) =
                    make_float2(acc[mt][nt][0] + b0, acc[mt][nt][1] + b1);
            if (r + 8 < M)
                *(float2*)(Cf + (size_t)(r + 8) * Ncol + c) =
                    make_float2(acc[mt][nt][2] + b0, acc[mt][nt][3] + b1);
        }
    }
}

// ---------------- fused GATv2 layer 1 ----------------
__global__ __launch_bounds__(256) void k_gat1(const float* __restrict__ att,
                                              const float* __restrict__ bias)
{
    const int node = blockIdx.x;
    const int t = threadIdx.x;
    __shared__ float xr_s[D1];
    __shared__ float att_s[D1];
    __shared__ float warp_part[8][4];
    __shared__ float sm_m[4], sm_d[4], sm_s[4], sm_w[4];

#pragma unroll
    for (int h = 0; h < HH; h++) {
        int ch = h * C1 + t;
        xr_s[ch]  = g_xr1[(size_t)node * D1 + ch];
        att_s[ch] = att[ch];
    }
    if (t < 4) { sm_m[t] = -1e30f; sm_d[t] = 0.f; }
    __syncthreads();

    float acc[HH] = {0.f, 0.f, 0.f, 0.f};
    const int beg = g_offs[node], end = g_offs[node + 1];

    for (int k = beg; k < end; k++) {
        const int e = g_perm[k];
        const int src = g_src[e];
        float xlv[HH], p[HH];
#pragma unroll
        for (int h = 0; h < HH; h++) {
            int ch = h * C1 + t;
            float xl = g_xl1[(size_t)src * D1 + ch];
            float v = xl + xr_s[ch] + g_ef1[(size_t)e * D1 + ch];
            float lv = v > 0.f ? v : 0.2f * v;
            xlv[h] = xl;
            p[h] = att_s[ch] * lv;
        }
#pragma unroll
        for (int h = 0; h < HH; h++)
#pragma unroll
            for (int off = 16; off; off >>= 1)
                p[h] += __shfl_xor_sync(0xffffffffu, p[h], off);
        if ((t & 31) == 0) {
            int w = t >> 5;
#pragma unroll
            for (int h = 0; h < HH; h++) warp_part[w][h] = p[h];
        }
        __syncthreads();
        if (t < 4) {
            float l = 0.f;
#pragma unroll
            for (int w = 0; w < 8; w++) l += warp_part[w][t];
            float mo = sm_m[t];
            float mn = fmaxf(mo, l);
            float sc = __expf(mo - mn);
            float wv = __expf(l - mn);
            sm_d[t] = sm_d[t] * sc + wv;
            sm_m[t] = mn;
            sm_s[t] = sc;
            sm_w[t] = wv;
        }
        __syncthreads();
#pragma unroll
        for (int h = 0; h < HH; h++) acc[h] = acc[h] * sm_s[h] + sm_w[h] * xlv[h];
    }

#pragma unroll
    for (int h = 0; h < HH; h++) {
        int ch = h * C1 + t;
        float o = acc[h] / (sm_d[h] + 1e-16f);
        float v = fmaxf(o + bias[ch], 0.f);
        bf16 hi = __float2bfloat16_rn(v);                 // hi/lo split for layer-2 GEMM
        g_h1h[(size_t)node * D1 + ch] = hi;
        g_h1l[(size_t)node * D1 + ch] = __float2bfloat16_rn(v - __bfloat162float(hi));
    }
}

// ---------------- fused GATv2 layer 2 ----------------
__global__ __launch_bounds__(256) void k_gat2(const float* __restrict__ att,
                                              const float* __restrict__ bias)
{
    const int node = blockIdx.x;
    const int t = threadIdx.x;
    __shared__ float xr_s[D2];
    __shared__ float att_s[D2];
    __shared__ float warp_part[8];
    __shared__ float sm_m[4], sm_d[4], sm_s[4], sm_w[4];

    xr_s[t]  = g_xr2[(size_t)node * D2 + t];
    att_s[t] = att[t];
    if (t < 4) { sm_m[t] = -1e30f; sm_d[t] = 0.f; }
    __syncthreads();

    float acc = 0.f;
    const int h = t >> 6;
    const int beg = g_offs[node], end = g_offs[node + 1];

    for (int k = beg; k < end; k++) {
        const int e = g_perm[k];
        const int src = g_src[e];
        float xl = g_xl2[(size_t)src * D2 + t];
        float v = xl + xr_s[t] + g_ef2[(size_t)e * D2 + t];
        float lv = v > 0.f ? v : 0.2f * v;
        float p = att_s[t] * lv;
#pragma unroll
        for (int off = 16; off; off >>= 1)
            p += __shfl_xor_sync(0xffffffffu, p, off);
        if ((t & 31) == 0) warp_part[t >> 5] = p;
        __syncthreads();
        if (t < 4) {
            float l = warp_part[2 * t] + warp_part[2 * t + 1];
            float mo = sm_m[t];
            float mn = fmaxf(mo, l);
            float sc = __expf(mo - mn);
            float wv = __expf(l - mn);
            sm_d[t] = sm_d[t] * sc + wv;
            sm_m[t] = mn;
            sm_s[t] = sc;
            sm_w[t] = wv;
        }
        __syncthreads();
        acc = acc * sm_s[h] + sm_w[h] * xl;
    }

    float o = acc / (sm_d[h] + 1e-16f);
    g_h2[(size_t)node * D2 + t] = fmaxf(o + bias[t], 0.f);
}

// ---------------- MLP head ----------------
__global__ void k_mlp(const void* __restrict__ n_nodes,
                      const float* __restrict__ fc1w, const float* __restrict__ fc1b,
                      const float* __restrict__ fc2w, const float* __restrict__ fc2b,
                      float* __restrict__ out)
{
    const int b = blockIdx.x;
    const int t = threadIdx.x;  // 64
    __shared__ float master[D2];
    __shared__ int s_last;
    __shared__ float ws[2];

    if (t == 0) {
        const int* w = (const int*)n_nodes;
        bool is64 = (w[1] == 0);
        long long cum = 0;
        if (is64) {
            const long long* l = (const long long*)n_nodes;
            for (int i = 0; i <= b; i++) cum += l[i];
        } else {
            for (int i = 0; i <= b; i++) cum += w[i];
        }
        s_last = (int)cum - 1;
    }
    __syncthreads();
    const int node = s_last;
    for (int i = t; i < D2; i += 64) master[i] = g_h2[(size_t)node * D2 + i];
    __syncthreads();

    float z = fc1b[t];
    for (int c = 0; c < D2; c++) z += master[c] * fc1w[c * 64 + t];
    z = fmaxf(z, 0.f);
    float v = z * fc2w[t];
#pragma unroll
    for (int off = 16; off; off >>= 1) v += __shfl_xor_sync(0xffffffffu, v, off);
    if ((t & 31) == 0) ws[t >> 5] = v;
    __syncthreads();
    if (t == 0) out[b] = ws[0] + ws[1] + fc2b[0];
}

// ---------------- launch ----------------
extern "C" void kernel_launch(void* const* d_in, const int* in_sizes, int n_in,
                              void* d_out, int out_size)
{
    const float* x    = (const float*)d_in[0];
    const void*  ei   = d_in[1];
    const float* ea   = (const float*)d_in[2];
    const void*  nnod = d_in[3];
    const float* Wl1  = (const float*)d_in[4];
    const float* bl1  = (const float*)d_in[5];
    const float* Wr1  = (const float*)d_in[6];
    const float* br1  = (const float*)d_in[7];
    const float* We1  = (const float*)d_in[8];
    const float* att1 = (const float*)d_in[9];
    const float* b1   = (const float*)d_in[10];
    const float* Wl2  = (const float*)d_in[11];
    const float* bl2  = (const float*)d_in[12];
    const float* Wr2  = (const float*)d_in[13];
    const float* br2  = (const float*)d_in[14];
    const float* We2  = (const float*)d_in[15];
    const float* att2 = (const float*)d_in[16];
    const float* b2   = (const float*)d_in[17];
    const float* fc1w = (const float*)d_in[18];
    const float* fc1b = (const float*)d_in[19];
    const float* fc2w = (const float*)d_in[20];
    const float* fc2b = (const float*)d_in[21];
    float* out = (float*)d_out;

    float *xl1, *xr1, *ef1, *xl2, *xr2, *ef2;
    bf16 *xh, *xlo, *eah, *eal, *h1h, *h1l;
    bf16 *wl1h, *wl1l, *wr1h, *wr1l, *we1h, *we1l;
    bf16 *wl2h, *wl2l, *wr2h, *wr2l, *we2h, *we2l;
    cudaGetSymbolAddress((void**)&xl1, g_xl1);
    cudaGetSymbolAddress((void**)&xr1, g_xr1);
    cudaGetSymbolAddress((void**)&ef1, g_ef1);
    cudaGetSymbolAddress((void**)&xl2, g_xl2);
    cudaGetSymbolAddress((void**)&xr2, g_xr2);
    cudaGetSymbolAddress((void**)&ef2, g_ef2);
    cudaGetSymbolAddress((void**)&xh,  g_xh);
    cudaGetSymbolAddress((void**)&xlo, g_xlo);
    cudaGetSymbolAddress((void**)&eah, g_eah);
    cudaGetSymbolAddress((void**)&eal, g_eal);
    cudaGetSymbolAddress((void**)&h1h, g_h1h);
    cudaGetSymbolAddress((void**)&h1l, g_h1l);
    cudaGetSymbolAddress((void**)&wl1h, g_wl1h); cudaGetSymbolAddress((void**)&wl1l, g_wl1l);
    cudaGetSymbolAddress((void**)&wr1h, g_wr1h); cudaGetSymbolAddress((void**)&wr1l, g_wr1l);
    cudaGetSymbolAddress((void**)&we1h, g_we1h); cudaGetSymbolAddress((void**)&we1l, g_we1l);
    cudaGetSymbolAddress((void**)&wl2h, g_wl2h); cudaGetSymbolAddress((void**)&wl2l, g_wl2l);
    cudaGetSymbolAddress((void**)&wr2h, g_wr2h); cudaGetSymbolAddress((void**)&wr2l, g_wr2l);
    cudaGetSymbolAddress((void**)&we2h, g_we2h); cudaGetSymbolAddress((void**)&we2l, g_we2l);

    cudaFuncSetAttribute(k_gemm_bf3<float>,
                         cudaFuncAttributeMaxDynamicSharedMemorySize, SMEM_BYTES);

    const int TB = 256;
    // CSR build
    k_zero<<<(NN + TB - 1) / TB, TB>>>();
    k_convert<<<(EE + TB - 1) / TB, TB>>>(ei);
    k_count<<<(EE + TB - 1) / TB, TB>>>();
    k_scanA<<<NB, 256>>>();
    k_scanB<<<1, 256>>>();
    k_scanC<<<NB, 256>>>();
    k_scatter<<<(EE + TB - 1) / TB, TB>>>();

    // hi/lo splits
    auto split = [&](const float* s, bf16* h, bf16* l, int n) {
        k_split<<<(n + 255) / 256, 256>>>(s, h, l, n);
    };
    split(x,   xh,  xlo, NN * 128);
    split(ea,  eah, eal, EE * 16);
    split(Wl1, wl1h, wl1l, 128 * 1024);
    split(Wr1, wr1h, wr1l, 128 * 1024);
    split(We1, we1h, we1l, 16 * 1024);
    split(Wl2, wl2h, wl2l, 1024 * 256);
    split(Wr2, wr2h, wr2l, 1024 * 256);
    split(We2, we2h, we2l, 16 * 256);

    // layer 1 projections
    {
        dim3 g1(D1 / 128, NN / 128);
        k_gemm_bf3<float><<<g1, 128, SMEM_BYTES>>>(xh, xlo, wl1h, wl1l, bl1, xl1, NN, 128, D1);
        k_gemm_bf3<float><<<g1, 128, SMEM_BYTES>>>(xh, xlo, wr1h, wr1l, br1, xr1, NN, 128, D1);
        dim3 ge(D1 / 128, (EE + 127) / 128);
        k_gemm_bf3<float><<<ge, 128, SMEM_BYTES>>>(eah, eal, we1h, we1l, nullptr, ef1, EE, 16, D1);
    }
    k_gat1<<<NN, 256>>>(att1, b1);

    // layer 2 projections
    {
        dim3 g2(D2 / 128, NN / 128);
        k_gemm_bf3<float><<<g2, 128, SMEM_BYTES>>>(h1h, h1l, wl2h, wl2l, bl2, xl2, NN, 1024, D2);
        k_gemm_bf3<float><<<g2, 128, SMEM_BYTES>>>(h1h, h1l, wr2h, wr2l, br2, xr2, NN, 1024, D2);
        dim3 ge(D2 / 128, (EE + 127) / 128);
        k_gemm_bf3<float><<<ge, 128, SMEM_BYTES>>>(eah, eal, we2h, we2l, nullptr, ef2, EE, 16, D2);
    }
    k_gat2<<<NN, 256>>>(att2, b2);

    k_mlp<<<BB, 64>>>(nnod, fc1w, fc1b, fc2w, fc2b, out);
}